// round 14
// baseline (speedup 1.0000x reference)
#include <cuda_runtime.h>
#include <cstdint>
#include <cstddef>

#define NN 100000
#define NE 600000
#define H 128
#define FIN 39

#define BM 128
#define BN 128
#define BK 32

#define N2 (2 * NN)
#define SCB 512
#define NB1 ((N2 + SCB - 1) / SCB)

// ---------------- scratch (device globals; no allocation allowed) ----------------
__device__ float g_h[(size_t)NN * H];
__device__ float g_PQ[(size_t)NN * 4 * H];
__device__ float g_S[(size_t)NN * 2 * H];
__device__ float g_deg[N2];
__device__ int g_cnt[N2];
__device__ int g_rp[N2 + 1];
__device__ int g_cur[N2];
__device__ int g_bsum[SCB];
__device__ __align__(16) float4 g_edges[2 * (size_t)NE];

__device__ __forceinline__ void cp16(uint32_t dst, const float* src) {
    asm volatile("cp.async.cg.shared.global [%0], [%1], 16;" :: "r"(dst), "l"(src));
}
__device__ __forceinline__ void ffma2(unsigned long long& d, unsigned long long a,
                                      unsigned long long b) {
    asm("fma.rn.f32x2 %0, %1, %2, %0;" : "+l"(d) : "l"(a), "l"(b));
}
__device__ __forceinline__ unsigned long long pack2(float x) {
    unsigned long long r;
    asm("mov.b64 %0, {%1, %1};" : "=l"(r) : "f"(x));
    return r;
}
__device__ __forceinline__ void unpack2(unsigned long long v, float& lo, float& hi) {
    asm("mov.b64 {%0, %1}, %2;" : "=f"(lo), "=f"(hi) : "l"(v));
}

// ---------------- utility kernels ----------------
__global__ void fill_zero(float4* __restrict__ p, int n4) {
    int i = blockIdx.x * blockDim.x + threadIdx.x;
    int stride = gridDim.x * blockDim.x;
    float4 z = make_float4(0.f, 0.f, 0.f, 0.f);
    for (; i < n4; i += stride) p[i] = z;
}

// ---------------- CSR build ----------------
__global__ void hist_kernel(const int* __restrict__ eia, const int* __restrict__ eie,
                            int* __restrict__ cnt) {
    int t = blockIdx.x * blockDim.x + threadIdx.x;
    if (t < NE) {
        atomicAdd(&cnt[eia[NE + t]], 1);
    } else if (t < 2 * NE) {
        atomicAdd(&cnt[NN + eie[t]], 1);
    }
}

__global__ void scan1(const int* __restrict__ cnt, int* __restrict__ rp,
                      int* __restrict__ bsum) {
    __shared__ int sh[SCB];
    int tid = threadIdx.x;
    int i = blockIdx.x * SCB + tid;
    int v = (i < N2) ? cnt[i] : 0;
    sh[tid] = v;
    __syncthreads();
    for (int off = 1; off < SCB; off <<= 1) {
        int t = (tid >= off) ? sh[tid - off] : 0;
        __syncthreads();
        sh[tid] += t;
        __syncthreads();
    }
    if (i < N2) rp[i] = sh[tid] - v;
    if (tid == SCB - 1) bsum[blockIdx.x] = sh[tid];
}

__global__ void scan2(int* __restrict__ bsum) {
    __shared__ int sh[SCB];
    int tid = threadIdx.x;
    int v = (tid < NB1) ? bsum[tid] : 0;
    sh[tid] = v;
    __syncthreads();
    for (int off = 1; off < SCB; off <<= 1) {
        int t = (tid >= off) ? sh[tid - off] : 0;
        __syncthreads();
        sh[tid] += t;
        __syncthreads();
    }
    if (tid < NB1) bsum[tid] = sh[tid] - v;
}

__global__ void scan3(const int* __restrict__ cnt, int* __restrict__ rp,
                      const int* __restrict__ bsum, int* __restrict__ cur,
                      float* __restrict__ deg) {
    int i = blockIdx.x * SCB + threadIdx.x;
    if (i < N2) {
        int e = rp[i] + bsum[blockIdx.x];
        rp[i] = e;
        cur[i] = e;
        deg[i] = (float)cnt[i];
    }
    if (i == 0) rp[N2] = 2 * NE;
}

__global__ void fill_csr(const int* __restrict__ eia, const float* __restrict__ eaa,
                         const int* __restrict__ eie, const float* __restrict__ eae,
                         int* __restrict__ cur, float4* __restrict__ edges) {
    int t = blockIdx.x * blockDim.x + threadIdx.x;
    if (t < NE) {
        int src = eia[t], tgt = eia[NE + t];
        int pos = atomicAdd(&cur[tgt], 1);
        edges[pos] = make_float4(__int_as_float(src), eaa[2 * t], eaa[2 * t + 1], 0.f);
    } else if (t < 2 * NE) {
        int e = t - NE;
        int src = eie[e], tgt = eie[NE + e];
        int pos = atomicAdd(&cur[NN + tgt], 1);
        edges[pos] = make_float4(__int_as_float(src), eae[2 * e], eae[2 * e + 1], 0.f);
    }
}

// ---------------- input projection ----------------
#define IPN 16
__global__ void __launch_bounds__(128) input_proj(const float* __restrict__ x,
                                                  const float* __restrict__ Win,
                                                  const float* __restrict__ bin,
                                                  float* __restrict__ h) {
    __shared__ float Ws[FIN * H];
    __shared__ __align__(16) float xs[IPN][FIN + 1];
    int tid = threadIdx.x;
    for (int i = tid; i < FIN * H; i += 128) Ws[i] = Win[i];
    int n0 = blockIdx.x * IPN;
    for (int i = tid; i < IPN * FIN; i += 128) {
        int r = i / FIN, c = i - r * FIN;
        xs[r][c] = x[(size_t)(n0 + r) * FIN + c];
    }
    __syncthreads();
    float acc[IPN];
    float bv = bin[tid];
#pragma unroll
    for (int r = 0; r < IPN; r++) acc[r] = bv;
#pragma unroll
    for (int k4 = 0; k4 < 9; k4++) {
        float wv0 = Ws[(k4 * 4 + 0) * H + tid];
        float wv1 = Ws[(k4 * 4 + 1) * H + tid];
        float wv2 = Ws[(k4 * 4 + 2) * H + tid];
        float wv3 = Ws[(k4 * 4 + 3) * H + tid];
#pragma unroll
        for (int r = 0; r < IPN; r++) {
            float4 xv = *(const float4*)&xs[r][k4 * 4];
            acc[r] = fmaf(xv.x, wv0, acc[r]);
            acc[r] = fmaf(xv.y, wv1, acc[r]);
            acc[r] = fmaf(xv.z, wv2, acc[r]);
            acc[r] = fmaf(xv.w, wv3, acc[r]);
        }
    }
#pragma unroll
    for (int k = 36; k < FIN; k++) {
        float wv = Ws[k * H + tid];
#pragma unroll
        for (int r = 0; r < IPN; r++) acc[r] = fmaf(xs[r][k], wv, acc[r]);
    }
#pragma unroll
    for (int r = 0; r < IPN; r++)
        h[(size_t)(n0 + r) * H + tid] = fmaxf(acc[r], 0.f);
}

// ---------------- CSR edge pass: warp per target node, 2-edge unroll (R11-proven) ----------
// weights loaded per-lane from global (L2-hot), no smem staging / block barrier
__global__ void __launch_bounds__(256) edge_csr(
    const int* __restrict__ rp, const float4* __restrict__ edges,
    const float* __restrict__ PQ,
    const float* __restrict__ w1ca, const float* __restrict__ w1ce,
    float* __restrict__ S) {
    unsigned gw = blockIdx.x * 8u + (threadIdx.x >> 5);
    int lane = threadIdx.x & 31;
    bool ally = gw < NN;
    int n = ally ? gw : gw - NN;
    size_t prow = (size_t)n * 512 + (ally ? 0 : 256);
    int qcol = ally ? 128 : 384;
    const float* wsrc = ally ? w1ca : w1ce;
    int start = rp[gw], end = rp[gw + 1];

    float4 w0 = *(const float4*)&wsrc[lane * 4];
    float4 w1 = *(const float4*)&wsrc[128 + lane * 4];
    float4 p = *(const float4*)&PQ[prow + lane * 4];
    float4 acc = make_float4(0.f, 0.f, 0.f, 0.f);

    int j = start;
    for (; j + 2 <= end; j += 2) {
        float4 er0 = edges[j];
        float4 er1 = edges[j + 1];
        int s0 = __float_as_int(er0.x);
        int s1 = __float_as_int(er1.x);
        float4 q0 = *(const float4*)&PQ[(size_t)s0 * 512 + qcol + lane * 4];
        float4 q1 = *(const float4*)&PQ[(size_t)s1 * 512 + qcol + lane * 4];
        float e00 = er0.y, e01 = er0.z;
        float e10 = er1.y, e11 = er1.z;
        acc.x += fmaxf(fmaf(e00, w0.x, fmaf(e01, w1.x, p.x + q0.x)), 0.f);
        acc.y += fmaxf(fmaf(e00, w0.y, fmaf(e01, w1.y, p.y + q0.y)), 0.f);
        acc.z += fmaxf(fmaf(e00, w0.z, fmaf(e01, w1.z, p.z + q0.z)), 0.f);
        acc.w += fmaxf(fmaf(e00, w0.w, fmaf(e01, w1.w, p.w + q0.w)), 0.f);
        acc.x += fmaxf(fmaf(e10, w0.x, fmaf(e11, w1.x, p.x + q1.x)), 0.f);
        acc.y += fmaxf(fmaf(e10, w0.y, fmaf(e11, w1.y, p.y + q1.y)), 0.f);
        acc.z += fmaxf(fmaf(e10, w0.z, fmaf(e11, w1.z, p.z + q1.z)), 0.f);
        acc.w += fmaxf(fmaf(e10, w0.w, fmaf(e11, w1.w, p.w + q1.w)), 0.f);
    }
    if (j < end) {
        float4 er = edges[j];
        int src = __float_as_int(er.x);
        float4 q = *(const float4*)&PQ[(size_t)src * 512 + qcol + lane * 4];
        float e0 = er.y, e1 = er.z;
        acc.x += fmaxf(fmaf(e0, w0.x, fmaf(e1, w1.x, p.x + q.x)), 0.f);
        acc.y += fmaxf(fmaf(e0, w0.y, fmaf(e1, w1.y, p.y + q.y)), 0.f);
        acc.z += fmaxf(fmaf(e0, w0.z, fmaf(e1, w1.z, p.z + q.z)), 0.f);
        acc.w += fmaxf(fmaf(e0, w0.w, fmaf(e1, w1.w, p.w + q.w)), 0.f);
    }
    *(float4*)&S[(size_t)n * 256 + (ally ? 0 : 128) + lane * 4] = acc;
}

// ---------------- gemm0: PQ projections (R4-proven config) ----------------
__global__ void __launch_bounds__(128, 2) gemm0_kernel(
    const float* __restrict__ A,
    const float* __restrict__ B0, const float* __restrict__ B1,
    const float* __restrict__ B2, const float* __restrict__ B3,
    const float* __restrict__ bias0, const float* __restrict__ bias2,
    float* __restrict__ out) {
    extern __shared__ float sm[];
    float(*As)[BK][BM + 4] = (float(*)[BK][BM + 4])sm;
    float(*Bs)[BK][BN] = (float(*)[BK][BN])(sm + 2 * BK * (BM + 4));

    int tid = threadIdx.x;
    int tx = tid & 15;
    int ty = tid >> 4;
    int row0 = blockIdx.x * BM;

    int y = blockIdx.y;
    const float* B = (y == 0) ? B0 : (y == 1) ? B1 : (y == 2) ? B2 : B3;
    const float* bias = (y == 0) ? bias0 : (y == 2) ? bias2 : nullptr;
    int ocol = y * BN;

    int agr = row0 + tid;
    bool aval = agr < NN;
    const float* Aptr = A + (size_t)(aval ? agr : 0) * H;
    int bk0 = tid >> 4;
    int bc = (tid & 15) * 8;

    uint32_t bs_base = (uint32_t)__cvta_generic_to_shared(&Bs[0][0][0]);

#pragma unroll
    for (int i = 0; i < 4; i++) {
        int k = bk0 + i * 8;
        const float* s = B + (size_t)k * H + bc;
        uint32_t d = bs_base + (unsigned)(k * BN + bc) * 4u;
        cp16(d, s);
        cp16(d + 16, s + 4);
    }
    asm volatile("cp.async.commit_group;" ::: "memory");

    float4 pa[8];
#pragma unroll
    for (int j = 0; j < 8; j++) pa[j] = *(const float4*)(Aptr + j * 4);

    unsigned long long acc[8][8];
#pragma unroll
    for (int rp2 = 0; rp2 < 8; rp2++)
#pragma unroll
        for (int c = 0; c < 8; c++) acc[rp2][c] = 0ull;

    for (int it = 0; it < 4; it++) {
        int buf = it & 1;
        asm volatile("cp.async.wait_group 0;" ::: "memory");
#pragma unroll
        for (int j = 0; j < 8; j++) {
            int k0 = j * 4;
            As[buf][k0 + 0][tid] = pa[j].x;
            As[buf][k0 + 1][tid] = pa[j].y;
            As[buf][k0 + 2][tid] = pa[j].z;
            As[buf][k0 + 3][tid] = pa[j].w;
        }
        if (it + 1 < 4) {
            const float* ap = Aptr + (it + 1) * BK;
#pragma unroll
            for (int j = 0; j < 8; j++) pa[j] = *(const float4*)(ap + j * 4);
        }
        __syncthreads();
        if (it + 1 < 4) {
            int kk = (it + 1) * BK;
            uint32_t bb = bs_base + (unsigned)((buf ^ 1) * BK * BN) * 4u;
#pragma unroll
            for (int i = 0; i < 4; i++) {
                int k = bk0 + i * 8;
                const float* s = B + (size_t)(kk + k) * H + bc;
                uint32_t d = bb + (unsigned)(k * BN + bc) * 4u;
                cp16(d, s);
                cp16(d + 16, s + 4);
            }
            asm volatile("cp.async.commit_group;" ::: "memory");
        }
#pragma unroll 4
        for (int k = 0; k < BK; k++) {
            unsigned long long a2[8];
            const ulonglong2* arow = (const ulonglong2*)&As[buf][k][ty * 16];
#pragma unroll
            for (int j = 0; j < 4; j++) {
                ulonglong2 v = arow[j];
                a2[j * 2] = v.x;
                a2[j * 2 + 1] = v.y;
            }
            float b[8];
            *(float4*)&b[0] = *(const float4*)&Bs[buf][k][tx * 8];
            *(float4*)&b[4] = *(const float4*)&Bs[buf][k][tx * 8 + 4];
            unsigned long long bp[8];
#pragma unroll
            for (int c = 0; c < 8; c++) bp[c] = pack2(b[c]);
#pragma unroll
            for (int rp2 = 0; rp2 < 8; rp2++)
#pragma unroll
                for (int c = 0; c < 8; c++) ffma2(acc[rp2][c], a2[rp2], bp[c]);
        }
    }

    int col0 = tx * 8;
    float bv[8];
#pragma unroll
    for (int c = 0; c < 8; c++) bv[c] = bias ? bias[col0 + c] : 0.f;
#pragma unroll
    for (int rp2 = 0; rp2 < 8; rp2++) {
        float vlo[8], vhi[8];
#pragma unroll
        for (int c = 0; c < 8; c++) unpack2(acc[rp2][c], vlo[c], vhi[c]);
        int gr0 = row0 + ty * 16 + rp2 * 2;
#pragma unroll
        for (int h2 = 0; h2 < 2; h2++) {
            int gr = gr0 + h2;
            const float* v = h2 ? vhi : vlo;
            if (gr < NN) {
                float o[8];
#pragma unroll
                for (int c = 0; c < 8; c++) o[c] = v[c] + bv[c];
                *(float4*)&out[(size_t)gr * 512 + ocol + col0] = *(float4*)o;
                *(float4*)&out[(size_t)gr * 512 + ocol + col0 + 4] = *(float4*)(o + 4);
            }
        }
    }
}

// ---------------- fused gemm12 (R11-proven) ----------------
#define SM12_FLOATS 24832
__global__ void __launch_bounds__(128, 2) gemm12_kernel(
    const float* __restrict__ Sm,
    const float* __restrict__ B0, const float* __restrict__ B1,
    const float* __restrict__ Wc, const float* __restrict__ bc,
    const float* __restrict__ resid,
    const float* __restrict__ dega, const float* __restrict__ dege,
    const float* __restrict__ b2a, const float* __restrict__ b2e,
    const float* __restrict__ lng, const float* __restrict__ lnb,
    float* __restrict__ out) {
    extern __shared__ float sm[];
    float(*As)[BK][BM + 4] = (float(*)[BK][BM + 4])sm;
    float(*Bs)[BK][BN] = (float(*)[BK][BN])(sm + 8448);
    float* vsm = sm;
    float(*Bs2)[BK][BN] = (float(*)[BK][BN])(sm + 16640);

    int tid = threadIdx.x;
    int tx = tid & 15;
    int ty = tid >> 4;
    int row0 = blockIdx.x * BM;
    int col0 = tx * 8;

    int agr = row0 + tid;
    bool aval = agr < NN;
    const float* Aptr = Sm + (size_t)(aval ? agr : 0) * 256;
    int bk0 = tid >> 4;
    int bc8 = (tid & 15) * 8;

    uint32_t bs_base = (uint32_t)__cvta_generic_to_shared(&Bs[0][0][0]);
    uint32_t bs2_base = (uint32_t)__cvta_generic_to_shared(&Bs2[0][0][0]);

#pragma unroll
    for (int i = 0; i < 4; i++) {
        int k = bk0 + i * 8;
        const float* s = Wc + (size_t)k * H + bc8;
        uint32_t d = bs2_base + (unsigned)(k * BN + bc8) * 4u;
        cp16(d, s);
        cp16(d + 16, s + 4);
    }
#pragma unroll
    for (int i = 0; i < 4; i++) {
        int k = bk0 + i * 8;
        const float* s = B0 + (size_t)k * H + bc8;
        uint32_t d = bs_base + (unsigned)(k * BN + bc8) * 4u;
        cp16(d, s);
        cp16(d + 16, s + 4);
    }
    asm volatile("cp.async.commit_group;" ::: "memory");

    float4 pa[8];
#pragma unroll
    for (int j = 0; j < 8; j++) pa[j] = *(const float4*)(Aptr + j * 4);

    unsigned long long acc[8][8];
#pragma unroll
    for (int rp2 = 0; rp2 < 8; rp2++)
#pragma unroll
        for (int c = 0; c < 8; c++) acc[rp2][c] = 0ull;

    for (int it = 0; it < 8; it++) {
        int buf = it & 1;
        asm volatile("cp.async.wait_group 0;" ::: "memory");
#pragma unroll
        for (int j = 0; j < 8; j++) {
            int k0 = j * 4;
            As[buf][k0 + 0][tid] = pa[j].x;
            As[buf][k0 + 1][tid] = pa[j].y;
            As[buf][k0 + 2][tid] = pa[j].z;
            As[buf][k0 + 3][tid] = pa[j].w;
        }
        if (it + 1 < 8) {
            const float* ap = Aptr + (it + 1) * BK;
#pragma unroll
            for (int j = 0; j < 8; j++) pa[j] = *(const float4*)(ap + j * 4);
        }
        __syncthreads();
        if (it + 1 < 8) {
            int kb2 = (it + 1) * BK;
            const float* Bp = B0;
            int kk = kb2;
            if (kb2 >= H) { Bp = B1; kk = kb2 - H; }
            uint32_t bb = bs_base + (unsigned)((buf ^ 1) * BK * BN) * 4u;
#pragma unroll
            for (int i = 0; i < 4; i++) {
                int k = bk0 + i * 8;
                const float* s = Bp + (size_t)(kk + k) * H + bc8;
                uint32_t d = bb + (unsigned)(k * BN + bc8) * 4u;
                cp16(d, s);
                cp16(d + 16, s + 4);
            }
            asm volatile("cp.async.commit_group;" ::: "memory");
        }
#pragma unroll 4
        for (int k = 0; k < BK; k++) {
            unsigned long long a2[8];
            const ulonglong2* arow = (const ulonglong2*)&As[buf][k][ty * 16];
#pragma unroll
            for (int j = 0; j < 4; j++) {
                ulonglong2 v = arow[j];
                a2[j * 2] = v.x;
                a2[j * 2 + 1] = v.y;
            }
            float b[8];
            *(float4*)&b[0] = *(const float4*)&Bs[buf][k][tx * 8];
            *(float4*)&b[4] = *(const float4*)&Bs[buf][k][tx * 8 + 4];
            unsigned long long bp[8];
#pragma unroll
            for (int c = 0; c < 8; c++) bp[c] = pack2(b[c]);
#pragma unroll
            for (int rp2 = 0; rp2 < 8; rp2++)
#pragma unroll
                for (int c = 0; c < 8; c++) ffma2(acc[rp2][c], a2[rp2], bp[c]);
        }
    }
    __syncthreads();

    // LN epilogue -> swizzled vsm
    {
        float b2av[8], b2ev[8], gv[8], bbv[8];
        *(float4*)&b2av[0] = *(const float4*)&b2a[col0];
        *(float4*)&b2av[4] = *(const float4*)&b2a[col0 + 4];
        *(float4*)&b2ev[0] = *(const float4*)&b2e[col0];
        *(float4*)&b2ev[4] = *(const float4*)&b2e[col0 + 4];
        *(float4*)&gv[0] = *(const float4*)&lng[col0];
        *(float4*)&gv[4] = *(const float4*)&lng[col0 + 4];
        *(float4*)&bbv[0] = *(const float4*)&lnb[col0];
        *(float4*)&bbv[4] = *(const float4*)&lnb[col0 + 4];
        int swzst = (tx & 7) << 2;
#pragma unroll
        for (int rp2 = 0; rp2 < 8; rp2++) {
            float vlo[8], vhi[8];
#pragma unroll
            for (int c = 0; c < 8; c++) unpack2(acc[rp2][c], vlo[c], vhi[c]);
#pragma unroll
            for (int h2 = 0; h2 < 2; h2++) {
                int rl = ty * 16 + rp2 * 2 + h2;
                int gr = row0 + rl;
                bool valid = gr < NN;
                float da = valid ? dega[gr] : 0.f;
                float de = valid ? dege[gr] : 0.f;
                float rs[8];
                if (valid) {
                    *(float4*)&rs[0] = *(const float4*)&resid[(size_t)gr * H + col0];
                    *(float4*)&rs[4] = *(const float4*)&resid[(size_t)gr * H + col0 + 4];
                } else {
#pragma unroll
                    for (int c = 0; c < 8; c++) rs[c] = 0.f;
                }
                float* vv = h2 ? vhi : vlo;
                float v[8];
                float s = 0.f, s2 = 0.f;
#pragma unroll
                for (int c = 0; c < 8; c++) {
                    v[c] = vv[c] + rs[c] + da * b2av[c] + de * b2ev[c];
                    s += v[c];
                    s2 += v[c] * v[c];
                }
#pragma unroll
                for (int off = 8; off; off >>= 1) {
                    s += __shfl_xor_sync(0xffffffffu, s, off);
                    s2 += __shfl_xor_sync(0xffffffffu, s2, off);
                }
                float mu = s * (1.f / 128.f);
                float var = s2 * (1.f / 128.f) - mu * mu;
                float rstd = rsqrtf(var + 1e-5f);
                int rsw = rl ^ swzst;
#pragma unroll
                for (int c = 0; c < 8; c++) {
                    float o = (v[c] - mu) * rstd * gv[c] + bbv[c];
                    vsm[(col0 + c) * 128 + rsw] = o;
                }
            }
        }
    }
    __syncthreads();

    // second GEMM
#pragma unroll
    for (int rp2 = 0; rp2 < 8; rp2++)
#pragma unroll
        for (int c = 0; c < 8; c++) acc[rp2][c] = 0ull;

    for (int it2 = 0; it2 < 4; it2++) {
        int buf = it2 & 1;
        asm volatile("cp.async.wait_group 0;" ::: "memory");
        __syncthreads();
        if (it2 + 1 < 4) {
            int kk = (it2 + 1) * BK;
            uint32_t bb = bs2_base + (unsigned)((buf ^ 1) * BK * BN) * 4u;
#pragma unroll
            for (int i = 0; i < 4; i++) {
                int k = bk0 + i * 8;
                const float* s = Wc + (size_t)(kk + k) * H + bc8;
                uint32_t d = bb + (unsigned)(k * BN + bc8) * 4u;
                cp16(d, s);
                cp16(d + 16, s + 4);
            }
            asm volatile("cp.async.commit_group;" ::: "memory");
        }
#pragma unroll 4
        for (int k = 0; k < BK; k++) {
            int kk = it2 * BK + k;
            int swzk = ((kk >> 3) & 7) << 2;
            unsigned long long a2[8];
#pragma unroll
            for (int j = 0; j < 4; j++) {
                ulonglong2 v = *(const ulonglong2*)&vsm[kk * 128 + ((ty * 16 + j * 4) ^ swzk)];
                a2[j * 2] = v.x;
                a2[j * 2 + 1] = v.y;
            }
            float b[8];
            *(float4*)&b[0] = *(const float4*)&Bs2[buf][k][tx * 8];
            *(float4*)&b[4] = *(const float4*)&Bs2[buf][k][tx * 8 + 4];
            unsigned long long bp[8];
#pragma unroll
            for (int c = 0; c < 8; c++) bp[c] = pack2(b[c]);
#pragma unroll
            for (int rp2 = 0; rp2 < 8; rp2++)
#pragma unroll
                for (int c = 0; c < 8; c++) ffma2(acc[rp2][c], a2[rp2], bp[c]);
        }
    }

    {
        float bv[8];
#pragma unroll
        for (int c = 0; c < 8; c++) bv[c] = bc[col0 + c];
        int swzst = (tx & 7) << 2;
#pragma unroll
        for (int rp2 = 0; rp2 < 8; rp2++) {
            float vlo[8], vhi[8];
#pragma unroll
            for (int c = 0; c < 8; c++) unpack2(acc[rp2][c], vlo[c], vhi[c]);
#pragma unroll
            for (int h2 = 0; h2 < 2; h2++) {
                int rl = ty * 16 + rp2 * 2 + h2;
                int gr = row0 + rl;
                if (gr < NN) {
                    const float* v = h2 ? vhi : vlo;
                    int rsw = rl ^ swzst;
                    float o[8];
#pragma unroll
                    for (int c = 0; c < 8; c++) {
                        float vres = vsm[(col0 + c) * 128 + rsw];
                        o[c] = vres + fmaxf(v[c] + bv[c], 0.f);
                    }
                    *(float4*)&out[(size_t)gr * H + col0] = *(float4*)o;
                    *(float4*)&out[(size_t)gr * H + col0 + 4] = *(float4*)(o + 4);
                }
            }
        }
    }
}

// ---------------- launch ----------------
extern "C" void kernel_launch(void* const* d_in, const int* in_sizes, int n_in,
                              void* d_out, int out_size) {
    (void)in_sizes; (void)n_in; (void)out_size;
    const float* x       = (const float*)d_in[0];
    const int*   ally_ei = (const int*)d_in[1];
    const float* ally_ea = (const float*)d_in[2];
    const int*   enc_ei  = (const int*)d_in[3];
    const float* enc_ea  = (const float*)d_in[4];
    const float* W_in    = (const float*)d_in[5];
    const float* b_in    = (const float*)d_in[6];
    const float* ally_W1 = (const float*)d_in[7];
    const float* ally_b1 = (const float*)d_in[8];
    const float* ally_W2 = (const float*)d_in[9];
    const float* ally_b2 = (const float*)d_in[10];
    const float* enc_W1  = (const float*)d_in[11];
    const float* enc_b1  = (const float*)d_in[12];
    const float* enc_W2  = (const float*)d_in[13];
    const float* enc_b2  = (const float*)d_in[14];
    const float* ln_g    = (const float*)d_in[15];
    const float* ln_b    = (const float*)d_in[16];
    const float* comb_W  = (const float*)d_in[17];
    const float* comb_b  = (const float*)d_in[18];
    float* out = (float*)d_out;

    float *h, *PQ, *S, *deg;
    int *cnt, *rp, *cur, *bsum;
    float4* edges;
    cudaGetSymbolAddress((void**)&h, g_h);
    cudaGetSymbolAddress((void**)&PQ, g_PQ);
    cudaGetSymbolAddress((void**)&S, g_S);
    cudaGetSymbolAddress((void**)&deg, g_deg);
    cudaGetSymbolAddress((void**)&cnt, g_cnt);
    cudaGetSymbolAddress((void**)&rp, g_rp);
    cudaGetSymbolAddress((void**)&cur, g_cur);
    cudaGetSymbolAddress((void**)&bsum, g_bsum);
    cudaGetSymbolAddress((void**)&edges, g_edges);
    float* dega = deg;
    float* dege = deg + NN;

    const int SMEM = (2 * BK * (BM + 4) + 2 * BK * BN) * 4;  // 66560 B
    const int SMEM12 = SM12_FLOATS * 4;                      // 99328 B
    cudaFuncSetAttribute(gemm0_kernel, cudaFuncAttributeMaxDynamicSharedMemorySize, SMEM);
    cudaFuncSetAttribute(gemm12_kernel, cudaFuncAttributeMaxDynamicSharedMemorySize, SMEM12);

    const int nblk = (NN + BM - 1) / BM;  // 782

    // ---- CSR build (once; shared by both layers) ----
    fill_zero<<<64, 256>>>((float4*)cnt, N2 / 4);
    hist_kernel<<<(2 * NE + 255) / 256, 256>>>(ally_ei, enc_ei, cnt);
    scan1<<<NB1, SCB>>>(cnt, rp, bsum);
    scan2<<<1, SCB>>>(bsum);
    scan3<<<NB1, SCB>>>(cnt, rp, bsum, cur, deg);
    fill_csr<<<(2 * NE + 255) / 256, 256>>>(ally_ei, ally_ea, enc_ei, enc_ea, cur, edges);

    // input projection
    input_proj<<<NN / IPN, 128>>>(x, W_in, b_in, h);

    for (int i = 0; i < 2; i++) {
        const float* aW1 = ally_W1 + (size_t)i * 258 * H;
        const float* eW1 = enc_W1 + (size_t)i * 258 * H;

        // P/Q for both edge types
        gemm0_kernel<<<dim3(nblk, 4), 128, SMEM>>>(
            h, aW1, aW1 + 128 * H, eW1, eW1 + 128 * H,
            ally_b1 + i * H, enc_b1 + i * H, PQ);

        // CSR edge pass
        edge_csr<<<N2 / 8, 256>>>(rp, edges, PQ, aW1 + 256 * H, eW1 + 256 * H, S);

        // fused combine + LN + comb MLP
        float* dst = (i == 1) ? out : h;
        gemm12_kernel<<<nblk, 128, SMEM12>>>(
            S,
            ally_W2 + (size_t)i * H * H, enc_W2 + (size_t)i * H * H,
            comb_W + (size_t)i * H * H, comb_b + i * H,
            h, dega, dege,
            ally_b2 + i * H, enc_b2 + i * H,
            ln_g + i * H, ln_b + i * H,
            dst);
    }
}

// round 15
// speedup vs baseline: 1.0296x; 1.0296x over previous
#include <cuda_runtime.h>
#include <cstdint>
#include <cstddef>

#define NN 100000
#define NE 600000
#define H 128
#define FIN 39

#define BM 128
#define BN 128
#define BK 32

#define N2 (2 * NN)
#define SCB 512
#define NB1 ((N2 + SCB - 1) / SCB)

// ---------------- scratch (device globals; no allocation allowed) ----------------
__device__ float g_h[(size_t)NN * H];
__device__ float g_PQ[(size_t)NN * 4 * H];
__device__ float g_S[(size_t)NN * 2 * H];
__device__ float g_deg[N2];
__device__ int g_cnt[N2];
__device__ int g_rp[N2 + 1];
__device__ int g_cur[N2];
__device__ int g_bsum[SCB];
__device__ __align__(16) float4 g_edges[2 * (size_t)NE];

__device__ __forceinline__ void cp16(uint32_t dst, const float* src) {
    asm volatile("cp.async.cg.shared.global [%0], [%1], 16;" :: "r"(dst), "l"(src));
}
__device__ __forceinline__ void ffma2(unsigned long long& d, unsigned long long a,
                                      unsigned long long b) {
    asm("fma.rn.f32x2 %0, %1, %2, %0;" : "+l"(d) : "l"(a), "l"(b));
}
__device__ __forceinline__ unsigned long long pack2(float x) {
    unsigned long long r;
    asm("mov.b64 %0, {%1, %1};" : "=l"(r) : "f"(x));
    return r;
}
__device__ __forceinline__ void unpack2(unsigned long long v, float& lo, float& hi) {
    asm("mov.b64 {%0, %1}, %2;" : "=f"(lo), "=f"(hi) : "l"(v));
}

// ---------------- utility kernels ----------------
__global__ void fill_zero(float4* __restrict__ p, int n4) {
    int i = blockIdx.x * blockDim.x + threadIdx.x;
    int stride = gridDim.x * blockDim.x;
    float4 z = make_float4(0.f, 0.f, 0.f, 0.f);
    for (; i < n4; i += stride) p[i] = z;
}

// ---------------- CSR build ----------------
__global__ void hist_kernel(const int* __restrict__ eia, const int* __restrict__ eie,
                            int* __restrict__ cnt) {
    int t = blockIdx.x * blockDim.x + threadIdx.x;
    if (t < NE) {
        atomicAdd(&cnt[eia[NE + t]], 1);
    } else if (t < 2 * NE) {
        atomicAdd(&cnt[NN + eie[t]], 1);
    }
}

__global__ void scan1(const int* __restrict__ cnt, int* __restrict__ rp,
                      int* __restrict__ bsum) {
    __shared__ int sh[SCB];
    int tid = threadIdx.x;
    int i = blockIdx.x * SCB + tid;
    int v = (i < N2) ? cnt[i] : 0;
    sh[tid] = v;
    __syncthreads();
    for (int off = 1; off < SCB; off <<= 1) {
        int t = (tid >= off) ? sh[tid - off] : 0;
        __syncthreads();
        sh[tid] += t;
        __syncthreads();
    }
    if (i < N2) rp[i] = sh[tid] - v;
    if (tid == SCB - 1) bsum[blockIdx.x] = sh[tid];
}

__global__ void scan2(int* __restrict__ bsum) {
    __shared__ int sh[SCB];
    int tid = threadIdx.x;
    int v = (tid < NB1) ? bsum[tid] : 0;
    sh[tid] = v;
    __syncthreads();
    for (int off = 1; off < SCB; off <<= 1) {
        int t = (tid >= off) ? sh[tid - off] : 0;
        __syncthreads();
        sh[tid] += t;
        __syncthreads();
    }
    if (tid < NB1) bsum[tid] = sh[tid] - v;
}

__global__ void scan3(const int* __restrict__ cnt, int* __restrict__ rp,
                      const int* __restrict__ bsum, int* __restrict__ cur,
                      float* __restrict__ deg) {
    int i = blockIdx.x * SCB + threadIdx.x;
    if (i < N2) {
        int e = rp[i] + bsum[blockIdx.x];
        rp[i] = e;
        cur[i] = e;
        deg[i] = (float)cnt[i];
    }
    if (i == 0) rp[N2] = 2 * NE;
}

__global__ void fill_csr(const int* __restrict__ eia, const float* __restrict__ eaa,
                         const int* __restrict__ eie, const float* __restrict__ eae,
                         int* __restrict__ cur, float4* __restrict__ edges) {
    int t = blockIdx.x * blockDim.x + threadIdx.x;
    if (t < NE) {
        int src = eia[t], tgt = eia[NE + t];
        int pos = atomicAdd(&cur[tgt], 1);
        edges[pos] = make_float4(__int_as_float(src), eaa[2 * t], eaa[2 * t + 1], 0.f);
    } else if (t < 2 * NE) {
        int e = t - NE;
        int src = eie[e], tgt = eie[NE + e];
        int pos = atomicAdd(&cur[NN + tgt], 1);
        edges[pos] = make_float4(__int_as_float(src), eae[2 * e], eae[2 * e + 1], 0.f);
    }
}

// ---------------- input projection ----------------
#define IPN 16
__global__ void __launch_bounds__(128) input_proj(const float* __restrict__ x,
                                                  const float* __restrict__ Win,
                                                  const float* __restrict__ bin,
                                                  float* __restrict__ h) {
    __shared__ float Ws[FIN * H];
    __shared__ __align__(16) float xs[IPN][FIN + 1];
    int tid = threadIdx.x;
    for (int i = tid; i < FIN * H; i += 128) Ws[i] = Win[i];
    int n0 = blockIdx.x * IPN;
    for (int i = tid; i < IPN * FIN; i += 128) {
        int r = i / FIN, c = i - r * FIN;
        xs[r][c] = x[(size_t)(n0 + r) * FIN + c];
    }
    __syncthreads();
    float acc[IPN];
    float bv = bin[tid];
#pragma unroll
    for (int r = 0; r < IPN; r++) acc[r] = bv;
#pragma unroll
    for (int k4 = 0; k4 < 9; k4++) {
        float wv0 = Ws[(k4 * 4 + 0) * H + tid];
        float wv1 = Ws[(k4 * 4 + 1) * H + tid];
        float wv2 = Ws[(k4 * 4 + 2) * H + tid];
        float wv3 = Ws[(k4 * 4 + 3) * H + tid];
#pragma unroll
        for (int r = 0; r < IPN; r++) {
            float4 xv = *(const float4*)&xs[r][k4 * 4];
            acc[r] = fmaf(xv.x, wv0, acc[r]);
            acc[r] = fmaf(xv.y, wv1, acc[r]);
            acc[r] = fmaf(xv.z, wv2, acc[r]);
            acc[r] = fmaf(xv.w, wv3, acc[r]);
        }
    }
#pragma unroll
    for (int k = 36; k < FIN; k++) {
        float wv = Ws[k * H + tid];
#pragma unroll
        for (int r = 0; r < IPN; r++) acc[r] = fmaf(xs[r][k], wv, acc[r]);
    }
#pragma unroll
    for (int r = 0; r < IPN; r++)
        h[(size_t)(n0 + r) * H + tid] = fmaxf(acc[r], 0.f);
}

// ---------------- CSR edge pass (R11-proven: smem weights, 2-edge unroll) ----------------
__global__ void __launch_bounds__(256) edge_csr(
    const int* __restrict__ rp, const float4* __restrict__ edges,
    const float* __restrict__ PQ,
    const float* __restrict__ w1ca, const float* __restrict__ w1ce,
    float* __restrict__ S) {
    __shared__ __align__(16) float w[512];
    w[threadIdx.x] = w1ca[threadIdx.x];
    w[256 + threadIdx.x] = w1ce[threadIdx.x];
    __syncthreads();
    unsigned gw = blockIdx.x * 8u + (threadIdx.x >> 5);
    int lane = threadIdx.x & 31;
    bool ally = gw < NN;
    int n = ally ? gw : gw - NN;
    size_t prow = (size_t)n * 512 + (ally ? 0 : 256);
    int qcol = ally ? 128 : 384;
    int woff = ally ? 0 : 256;
    int start = rp[gw], end = rp[gw + 1];

    float4 p = *(const float4*)&PQ[prow + lane * 4];
    float4 w0 = *(const float4*)&w[woff + lane * 4];
    float4 w1 = *(const float4*)&w[woff + 128 + lane * 4];
    float4 acc = make_float4(0.f, 0.f, 0.f, 0.f);

    int j = start;
    for (; j + 2 <= end; j += 2) {
        float4 er0 = edges[j];
        float4 er1 = edges[j + 1];
        int s0 = __float_as_int(er0.x);
        int s1 = __float_as_int(er1.x);
        float4 q0 = *(const float4*)&PQ[(size_t)s0 * 512 + qcol + lane * 4];
        float4 q1 = *(const float4*)&PQ[(size_t)s1 * 512 + qcol + lane * 4];
        float e00 = er0.y, e01 = er0.z;
        float e10 = er1.y, e11 = er1.z;
        acc.x += fmaxf(fmaf(e00, w0.x, fmaf(e01, w1.x, p.x + q0.x)), 0.f);
        acc.y += fmaxf(fmaf(e00, w0.y, fmaf(e01, w1.y, p.y + q0.y)), 0.f);
        acc.z += fmaxf(fmaf(e00, w0.z, fmaf(e01, w1.z, p.z + q0.z)), 0.f);
        acc.w += fmaxf(fmaf(e00, w0.w, fmaf(e01, w1.w, p.w + q0.w)), 0.f);
        acc.x += fmaxf(fmaf(e10, w0.x, fmaf(e11, w1.x, p.x + q1.x)), 0.f);
        acc.y += fmaxf(fmaf(e10, w0.y, fmaf(e11, w1.y, p.y + q1.y)), 0.f);
        acc.z += fmaxf(fmaf(e10, w0.z, fmaf(e11, w1.z, p.z + q1.z)), 0.f);
        acc.w += fmaxf(fmaf(e10, w0.w, fmaf(e11, w1.w, p.w + q1.w)), 0.f);
    }
    if (j < end) {
        float4 er = edges[j];
        int src = __float_as_int(er.x);
        float4 q = *(const float4*)&PQ[(size_t)src * 512 + qcol + lane * 4];
        float e0 = er.y, e1 = er.z;
        acc.x += fmaxf(fmaf(e0, w0.x, fmaf(e1, w1.x, p.x + q.x)), 0.f);
        acc.y += fmaxf(fmaf(e0, w0.y, fmaf(e1, w1.y, p.y + q.y)), 0.f);
        acc.z += fmaxf(fmaf(e0, w0.z, fmaf(e1, w1.z, p.z + q.z)), 0.f);
        acc.w += fmaxf(fmaf(e0, w0.w, fmaf(e1, w1.w, p.w + q.w)), 0.f);
    }
    *(float4*)&S[(size_t)n * 256 + (ally ? 0 : 128) + lane * 4] = acc;
}

// ---------------- gemm0: PQ projections (R4-proven config) ----------------
__global__ void __launch_bounds__(128, 2) gemm0_kernel(
    const float* __restrict__ A,
    const float* __restrict__ B0, const float* __restrict__ B1,
    const float* __restrict__ B2, const float* __restrict__ B3,
    const float* __restrict__ bias0, const float* __restrict__ bias2,
    float* __restrict__ out) {
    extern __shared__ float sm[];
    float(*As)[BK][BM + 4] = (float(*)[BK][BM + 4])sm;
    float(*Bs)[BK][BN] = (float(*)[BK][BN])(sm + 2 * BK * (BM + 4));

    int tid = threadIdx.x;
    int tx = tid & 15;
    int ty = tid >> 4;
    int row0 = blockIdx.x * BM;

    int y = blockIdx.y;
    const float* B = (y == 0) ? B0 : (y == 1) ? B1 : (y == 2) ? B2 : B3;
    const float* bias = (y == 0) ? bias0 : (y == 2) ? bias2 : nullptr;
    int ocol = y * BN;

    int agr = row0 + tid;
    bool aval = agr < NN;
    const float* Aptr = A + (size_t)(aval ? agr : 0) * H;
    int bk0 = tid >> 4;
    int bc = (tid & 15) * 8;

    uint32_t bs_base = (uint32_t)__cvta_generic_to_shared(&Bs[0][0][0]);

#pragma unroll
    for (int i = 0; i < 4; i++) {
        int k = bk0 + i * 8;
        const float* s = B + (size_t)k * H + bc;
        uint32_t d = bs_base + (unsigned)(k * BN + bc) * 4u;
        cp16(d, s);
        cp16(d + 16, s + 4);
    }
    asm volatile("cp.async.commit_group;" ::: "memory");

    float4 pa[8];
#pragma unroll
    for (int j = 0; j < 8; j++) pa[j] = *(const float4*)(Aptr + j * 4);

    unsigned long long acc[8][8];
#pragma unroll
    for (int rp2 = 0; rp2 < 8; rp2++)
#pragma unroll
        for (int c = 0; c < 8; c++) acc[rp2][c] = 0ull;

    for (int it = 0; it < 4; it++) {
        int buf = it & 1;
        asm volatile("cp.async.wait_group 0;" ::: "memory");
#pragma unroll
        for (int j = 0; j < 8; j++) {
            int k0 = j * 4;
            As[buf][k0 + 0][tid] = pa[j].x;
            As[buf][k0 + 1][tid] = pa[j].y;
            As[buf][k0 + 2][tid] = pa[j].z;
            As[buf][k0 + 3][tid] = pa[j].w;
        }
        if (it + 1 < 4) {
            const float* ap = Aptr + (it + 1) * BK;
#pragma unroll
            for (int j = 0; j < 8; j++) pa[j] = *(const float4*)(ap + j * 4);
        }
        __syncthreads();
        if (it + 1 < 4) {
            int kk = (it + 1) * BK;
            uint32_t bb = bs_base + (unsigned)((buf ^ 1) * BK * BN) * 4u;
#pragma unroll
            for (int i = 0; i < 4; i++) {
                int k = bk0 + i * 8;
                const float* s = B + (size_t)(kk + k) * H + bc;
                uint32_t d = bb + (unsigned)(k * BN + bc) * 4u;
                cp16(d, s);
                cp16(d + 16, s + 4);
            }
            asm volatile("cp.async.commit_group;" ::: "memory");
        }
#pragma unroll 4
        for (int k = 0; k < BK; k++) {
            unsigned long long a2[8];
            const ulonglong2* arow = (const ulonglong2*)&As[buf][k][ty * 16];
#pragma unroll
            for (int j = 0; j < 4; j++) {
                ulonglong2 v = arow[j];
                a2[j * 2] = v.x;
                a2[j * 2 + 1] = v.y;
            }
            float b[8];
            *(float4*)&b[0] = *(const float4*)&Bs[buf][k][tx * 8];
            *(float4*)&b[4] = *(const float4*)&Bs[buf][k][tx * 8 + 4];
            unsigned long long bp[8];
#pragma unroll
            for (int c = 0; c < 8; c++) bp[c] = pack2(b[c]);
#pragma unroll
            for (int rp2 = 0; rp2 < 8; rp2++)
#pragma unroll
                for (int c = 0; c < 8; c++) ffma2(acc[rp2][c], a2[rp2], bp[c]);
        }
    }

    int col0 = tx * 8;
    float bv[8];
#pragma unroll
    for (int c = 0; c < 8; c++) bv[c] = bias ? bias[col0 + c] : 0.f;
#pragma unroll
    for (int rp2 = 0; rp2 < 8; rp2++) {
        float vlo[8], vhi[8];
#pragma unroll
        for (int c = 0; c < 8; c++) unpack2(acc[rp2][c], vlo[c], vhi[c]);
        int gr0 = row0 + ty * 16 + rp2 * 2;
#pragma unroll
        for (int h2 = 0; h2 < 2; h2++) {
            int gr = gr0 + h2;
            const float* v = h2 ? vhi : vlo;
            if (gr < NN) {
                float o[8];
#pragma unroll
                for (int c = 0; c < 8; c++) o[c] = v[c] + bv[c];
                *(float4*)&out[(size_t)gr * 512 + ocol + col0] = *(float4*)o;
                *(float4*)&out[(size_t)gr * 512 + ocol + col0 + 4] = *(float4*)(o + 4);
            }
        }
    }
}

// ---------------- fused gemm12 (R11-proven) ----------------
#define SM12_FLOATS 24832
__global__ void __launch_bounds__(128, 2) gemm12_kernel(
    const float* __restrict__ Sm,
    const float* __restrict__ B0, const float* __restrict__ B1,
    const float* __restrict__ Wc, const float* __restrict__ bc,
    const float* __restrict__ resid,
    const float* __restrict__ dega, const float* __restrict__ dege,
    const float* __restrict__ b2a, const float* __restrict__ b2e,
    const float* __restrict__ lng, const float* __restrict__ lnb,
    float* __restrict__ out) {
    extern __shared__ float sm[];
    float(*As)[BK][BM + 4] = (float(*)[BK][BM + 4])sm;
    float(*Bs)[BK][BN] = (float(*)[BK][BN])(sm + 8448);
    float* vsm = sm;
    float(*Bs2)[BK][BN] = (float(*)[BK][BN])(sm + 16640);

    int tid = threadIdx.x;
    int tx = tid & 15;
    int ty = tid >> 4;
    int row0 = blockIdx.x * BM;
    int col0 = tx * 8;

    int agr = row0 + tid;
    bool aval = agr < NN;
    const float* Aptr = Sm + (size_t)(aval ? agr : 0) * 256;
    int bk0 = tid >> 4;
    int bc8 = (tid & 15) * 8;

    uint32_t bs_base = (uint32_t)__cvta_generic_to_shared(&Bs[0][0][0]);
    uint32_t bs2_base = (uint32_t)__cvta_generic_to_shared(&Bs2[0][0][0]);

#pragma unroll
    for (int i = 0; i < 4; i++) {
        int k = bk0 + i * 8;
        const float* s = Wc + (size_t)k * H + bc8;
        uint32_t d = bs2_base + (unsigned)(k * BN + bc8) * 4u;
        cp16(d, s);
        cp16(d + 16, s + 4);
    }
#pragma unroll
    for (int i = 0; i < 4; i++) {
        int k = bk0 + i * 8;
        const float* s = B0 + (size_t)k * H + bc8;
        uint32_t d = bs_base + (unsigned)(k * BN + bc8) * 4u;
        cp16(d, s);
        cp16(d + 16, s + 4);
    }
    asm volatile("cp.async.commit_group;" ::: "memory");

    float4 pa[8];
#pragma unroll
    for (int j = 0; j < 8; j++) pa[j] = *(const float4*)(Aptr + j * 4);

    unsigned long long acc[8][8];
#pragma unroll
    for (int rp2 = 0; rp2 < 8; rp2++)
#pragma unroll
        for (int c = 0; c < 8; c++) acc[rp2][c] = 0ull;

    for (int it = 0; it < 8; it++) {
        int buf = it & 1;
        asm volatile("cp.async.wait_group 0;" ::: "memory");
#pragma unroll
        for (int j = 0; j < 8; j++) {
            int k0 = j * 4;
            As[buf][k0 + 0][tid] = pa[j].x;
            As[buf][k0 + 1][tid] = pa[j].y;
            As[buf][k0 + 2][tid] = pa[j].z;
            As[buf][k0 + 3][tid] = pa[j].w;
        }
        if (it + 1 < 8) {
            const float* ap = Aptr + (it + 1) * BK;
#pragma unroll
            for (int j = 0; j < 8; j++) pa[j] = *(const float4*)(ap + j * 4);
        }
        __syncthreads();
        if (it + 1 < 8) {
            int kb2 = (it + 1) * BK;
            const float* Bp = B0;
            int kk = kb2;
            if (kb2 >= H) { Bp = B1; kk = kb2 - H; }
            uint32_t bb = bs_base + (unsigned)((buf ^ 1) * BK * BN) * 4u;
#pragma unroll
            for (int i = 0; i < 4; i++) {
                int k = bk0 + i * 8;
                const float* s = Bp + (size_t)(kk + k) * H + bc8;
                uint32_t d = bb + (unsigned)(k * BN + bc8) * 4u;
                cp16(d, s);
                cp16(d + 16, s + 4);
            }
            asm volatile("cp.async.commit_group;" ::: "memory");
        }
#pragma unroll 4
        for (int k = 0; k < BK; k++) {
            unsigned long long a2[8];
            const ulonglong2* arow = (const ulonglong2*)&As[buf][k][ty * 16];
#pragma unroll
            for (int j = 0; j < 4; j++) {
                ulonglong2 v = arow[j];
                a2[j * 2] = v.x;
                a2[j * 2 + 1] = v.y;
            }
            float b[8];
            *(float4*)&b[0] = *(const float4*)&Bs[buf][k][tx * 8];
            *(float4*)&b[4] = *(const float4*)&Bs[buf][k][tx * 8 + 4];
            unsigned long long bp[8];
#pragma unroll
            for (int c = 0; c < 8; c++) bp[c] = pack2(b[c]);
#pragma unroll
            for (int rp2 = 0; rp2 < 8; rp2++)
#pragma unroll
                for (int c = 0; c < 8; c++) ffma2(acc[rp2][c], a2[rp2], bp[c]);
        }
    }
    __syncthreads();

    // LN epilogue -> swizzled vsm
    {
        float b2av[8], b2ev[8], gv[8], bbv[8];
        *(float4*)&b2av[0] = *(const float4*)&b2a[col0];
        *(float4*)&b2av[4] = *(const float4*)&b2a[col0 + 4];
        *(float4*)&b2ev[0] = *(const float4*)&b2e[col0];
        *(float4*)&b2ev[4] = *(const float4*)&b2e[col0 + 4];
        *(float4*)&gv[0] = *(const float4*)&lng[col0];
        *(float4*)&gv[4] = *(const float4*)&lng[col0 + 4];
        *(float4*)&bbv[0] = *(const float4*)&lnb[col0];
        *(float4*)&bbv[4] = *(const float4*)&lnb[col0 + 4];
        int swzst = (tx & 7) << 2;
#pragma unroll
        for (int rp2 = 0; rp2 < 8; rp2++) {
            float vlo[8], vhi[8];
#pragma unroll
            for (int c = 0; c < 8; c++) unpack2(acc[rp2][c], vlo[c], vhi[c]);
#pragma unroll
            for (int h2 = 0; h2 < 2; h2++) {
                int rl = ty * 16 + rp2 * 2 + h2;
                int gr = row0 + rl;
                bool valid = gr < NN;
                float da = valid ? dega[gr] : 0.f;
                float de = valid ? dege[gr] : 0.f;
                float rs[8];
                if (valid) {
                    *(float4*)&rs[0] = *(const float4*)&resid[(size_t)gr * H + col0];
                    *(float4*)&rs[4] = *(const float4*)&resid[(size_t)gr * H + col0 + 4];
                } else {
#pragma unroll
                    for (int c = 0; c < 8; c++) rs[c] = 0.f;
                }
                float* vv = h2 ? vhi : vlo;
                float v[8];
                float s = 0.f, s2 = 0.f;
#pragma unroll
                for (int c = 0; c < 8; c++) {
                    v[c] = vv[c] + rs[c] + da * b2av[c] + de * b2ev[c];
                    s += v[c];
                    s2 += v[c] * v[c];
                }
#pragma unroll
                for (int off = 8; off; off >>= 1) {
                    s += __shfl_xor_sync(0xffffffffu, s, off);
                    s2 += __shfl_xor_sync(0xffffffffu, s2, off);
                }
                float mu = s * (1.f / 128.f);
                float var = s2 * (1.f / 128.f) - mu * mu;
                float rstd = rsqrtf(var + 1e-5f);
                int rsw = rl ^ swzst;
#pragma unroll
                for (int c = 0; c < 8; c++) {
                    float o = (v[c] - mu) * rstd * gv[c] + bbv[c];
                    vsm[(col0 + c) * 128 + rsw] = o;
                }
            }
        }
    }
    __syncthreads();

    // second GEMM
#pragma unroll
    for (int rp2 = 0; rp2 < 8; rp2++)
#pragma unroll
        for (int c = 0; c < 8; c++) acc[rp2][c] = 0ull;

    for (int it2 = 0; it2 < 4; it2++) {
        int buf = it2 & 1;
        asm volatile("cp.async.wait_group 0;" ::: "memory");
        __syncthreads();
        if (it2 + 1 < 4) {
            int kk = (it2 + 1) * BK;
            uint32_t bb = bs2_base + (unsigned)((buf ^ 1) * BK * BN) * 4u;
#pragma unroll
            for (int i = 0; i < 4; i++) {
                int k = bk0 + i * 8;
                const float* s = Wc + (size_t)(kk + k) * H + bc8;
                uint32_t d = bb + (unsigned)(k * BN + bc8) * 4u;
                cp16(d, s);
                cp16(d + 16, s + 4);
            }
            asm volatile("cp.async.commit_group;" ::: "memory");
        }
#pragma unroll 4
        for (int k = 0; k < BK; k++) {
            int kk = it2 * BK + k;
            int swzk = ((kk >> 3) & 7) << 2;
            unsigned long long a2[8];
#pragma unroll
            for (int j = 0; j < 4; j++) {
                ulonglong2 v = *(const ulonglong2*)&vsm[kk * 128 + ((ty * 16 + j * 4) ^ swzk)];
                a2[j * 2] = v.x;
                a2[j * 2 + 1] = v.y;
            }
            float b[8];
            *(float4*)&b[0] = *(const float4*)&Bs2[buf][k][tx * 8];
            *(float4*)&b[4] = *(const float4*)&Bs2[buf][k][tx * 8 + 4];
            unsigned long long bp[8];
#pragma unroll
            for (int c = 0; c < 8; c++) bp[c] = pack2(b[c]);
#pragma unroll
            for (int rp2 = 0; rp2 < 8; rp2++)
#pragma unroll
                for (int c = 0; c < 8; c++) ffma2(acc[rp2][c], a2[rp2], bp[c]);
        }
    }

    {
        float bv[8];
#pragma unroll
        for (int c = 0; c < 8; c++) bv[c] = bc[col0 + c];
        int swzst = (tx & 7) << 2;
#pragma unroll
        for (int rp2 = 0; rp2 < 8; rp2++) {
            float vlo[8], vhi[8];
#pragma unroll
            for (int c = 0; c < 8; c++) unpack2(acc[rp2][c], vlo[c], vhi[c]);
#pragma unroll
            for (int h2 = 0; h2 < 2; h2++) {
                int rl = ty * 16 + rp2 * 2 + h2;
                int gr = row0 + rl;
                if (gr < NN) {
                    const float* v = h2 ? vhi : vlo;
                    int rsw = rl ^ swzst;
                    float o[8];
#pragma unroll
                    for (int c = 0; c < 8; c++) {
                        float vres = vsm[(col0 + c) * 128 + rsw];
                        o[c] = vres + fmaxf(v[c] + bv[c], 0.f);
                    }
                    *(float4*)&out[(size_t)gr * H + col0] = *(float4*)o;
                    *(float4*)&out[(size_t)gr * H + col0 + 4] = *(float4*)(o + 4);
                }
            }
        }
    }
}

// ---------------- launch ----------------
extern "C" void kernel_launch(void* const* d_in, const int* in_sizes, int n_in,
                              void* d_out, int out_size) {
    (void)in_sizes; (void)n_in; (void)out_size;
    const float* x       = (const float*)d_in[0];
    const int*   ally_ei = (const int*)d_in[1];
    const float* ally_ea = (const float*)d_in[2];
    const int*   enc_ei  = (const int*)d_in[3];
    const float* enc_ea  = (const float*)d_in[4];
    const float* W_in    = (const float*)d_in[5];
    const float* b_in    = (const float*)d_in[6];
    const float* ally_W1 = (const float*)d_in[7];
    const float* ally_b1 = (const float*)d_in[8];
    const float* ally_W2 = (const float*)d_in[9];
    const float* ally_b2 = (const float*)d_in[10];
    const float* enc_W1  = (const float*)d_in[11];
    const float* enc_b1  = (const float*)d_in[12];
    const float* enc_W2  = (const float*)d_in[13];
    const float* enc_b2  = (const float*)d_in[14];
    const float* ln_g    = (const float*)d_in[15];
    const float* ln_b    = (const float*)d_in[16];
    const float* comb_W  = (const float*)d_in[17];
    const float* comb_b  = (const float*)d_in[18];
    float* out = (float*)d_out;

    float *h, *PQ, *S, *deg;
    int *cnt, *rp, *cur, *bsum;
    float4* edges;
    cudaGetSymbolAddress((void**)&h, g_h);
    cudaGetSymbolAddress((void**)&PQ, g_PQ);
    cudaGetSymbolAddress((void**)&S, g_S);
    cudaGetSymbolAddress((void**)&deg, g_deg);
    cudaGetSymbolAddress((void**)&cnt, g_cnt);
    cudaGetSymbolAddress((void**)&rp, g_rp);
    cudaGetSymbolAddress((void**)&cur, g_cur);
    cudaGetSymbolAddress((void**)&bsum, g_bsum);
    cudaGetSymbolAddress((void**)&edges, g_edges);
    float* dega = deg;
    float* dege = deg + NN;

    const int SMEM = (2 * BK * (BM + 4) + 2 * BK * BN) * 4;  // 66560 B
    const int SMEM12 = SM12_FLOATS * 4;                      // 99328 B
    cudaFuncSetAttribute(gemm0_kernel, cudaFuncAttributeMaxDynamicSharedMemorySize, SMEM);
    cudaFuncSetAttribute(gemm12_kernel, cudaFuncAttributeMaxDynamicSharedMemorySize, SMEM12);

    const int nblk = (NN + BM - 1) / BM;  // 782

    // ---- CSR build (once; shared by both layers) ----
    fill_zero<<<64, 256>>>((float4*)cnt, N2 / 4);
    hist_kernel<<<(2 * NE + 255) / 256, 256>>>(ally_ei, enc_ei, cnt);
    scan1<<<NB1, SCB>>>(cnt, rp, bsum);
    scan2<<<1, SCB>>>(bsum);
    scan3<<<NB1, SCB>>>(cnt, rp, bsum, cur, deg);
    fill_csr<<<(2 * NE + 255) / 256, 256>>>(ally_ei, ally_ea, enc_ei, enc_ea, cur, edges);

    // input projection
    input_proj<<<NN / IPN, 128>>>(x, W_in, b_in, h);

    for (int i = 0; i < 2; i++) {
        const float* aW1 = ally_W1 + (size_t)i * 258 * H;
        const float* eW1 = enc_W1 + (size_t)i * 258 * H;

        // P/Q for both edge types
        gemm0_kernel<<<dim3(nblk, 4), 128, SMEM>>>(
            h, aW1, aW1 + 128 * H, eW1, eW1 + 128 * H,
            ally_b1 + i * H, enc_b1 + i * H, PQ);

        // CSR edge pass
        edge_csr<<<N2 / 8, 256>>>(rp, edges, PQ, aW1 + 256 * H, eW1 + 256 * H, S);

        // fused combine + LN + comb MLP
        float* dst = (i == 1) ? out : h;
        gemm12_kernel<<<nblk, 128, SMEM12>>>(
            S,
            ally_W2 + (size_t)i * H * H, enc_W2 + (size_t)i * H * H,
            comb_W + (size_t)i * H * H, comb_b + i * H,
            h, dega, dege,
            ally_b2 + i * H, enc_b2 + i * H,
            ln_g + i * H, ln_b + i * H,
            dst);
    }
}